// round 13
// baseline (speedup 1.0000x reference)
#include <cuda_runtime.h>
#include <cuda_fp16.h>
#include <cstdint>

// Problem dims (fixed by the reference)
#define SEQL   2048
#define NMODEL 4096
#define HEADS  32
#define DHEAD  128
#define MCACHE 4096
#define LOG2E  1.4426950408889634f

// ======================= family-portable PTX helpers =======================
__device__ __forceinline__ uint32_t smem_to_u32(const void* p) {
    uint32_t a;
    asm("{ .reg .u64 t; cvta.to.shared.u64 t, %1; cvt.u32.u64 %0, t; }"
        : "=r"(a) : "l"(p));
    return a;
}
__device__ __forceinline__ void mma_f16(float* c, const uint32_t* a, const uint32_t* b) {
    asm volatile(
        "mma.sync.aligned.m16n8k16.row.col.f32.f16.f16.f32 "
        "{%0,%1,%2,%3}, {%4,%5,%6,%7}, {%8,%9}, {%0,%1,%2,%3};"
        : "+f"(c[0]), "+f"(c[1]), "+f"(c[2]), "+f"(c[3])
        : "r"(a[0]), "r"(a[1]), "r"(a[2]), "r"(a[3]), "r"(b[0]), "r"(b[1]));
}
__device__ __forceinline__ void ldmat4(uint32_t* r, uint32_t addr) {
    asm volatile("ldmatrix.sync.aligned.m8n8.x4.shared.b16 {%0,%1,%2,%3}, [%4];"
        : "=r"(r[0]), "=r"(r[1]), "=r"(r[2]), "=r"(r[3]) : "r"(addr));
}
__device__ __forceinline__ void cpasync16(uint32_t dst, const void* src) {
    asm volatile("cp.async.cg.shared.global [%0], [%1], 16;" :: "r"(dst), "l"(src));
}
#define CP_COMMIT() asm volatile("cp.async.commit_group;" ::: "memory")
#define CP_WAIT(n)  asm volatile("cp.async.wait_group %0;" :: "n"(n) : "memory")

// pack two f32 -> f16x2 register (low half = first arg)
__device__ __forceinline__ uint32_t packh2(float lo, float hi) {
    uint32_t r;
    asm("cvt.rn.f16x2.f32 %0, %1, %2;" : "=r"(r) : "f"(hi), "f"(lo));
    return r;
}
__device__ __forceinline__ float2 h2f2(uint32_t u) {
    __half2 h = *reinterpret_cast<__half2*>(&u);
    return __half22float2(h);
}
// MUFU.EX2 (base-2 exp, approx: 2^-22 rel err — far below our budget)
__device__ __forceinline__ float ex2f(float x) {
    float y;
    asm("ex2.approx.f32 %0, %1;" : "=f"(y) : "f"(x));
    return y;
}

// ======================= scratch (device globals) =======================
__device__ __half g_Qhi[(size_t)HEADS * SEQL * DHEAD];
__device__ __half g_Qlo[(size_t)HEADS * SEQL * DHEAD];
__device__ __half g_Khi[(size_t)HEADS * MCACHE * DHEAD];   // pre-scaled by LOG2E
__device__ __half g_Klo[(size_t)HEADS * MCACHE * DHEAD];
__device__ __half g_Vt[(size_t)HEADS * DHEAD * MCACHE];    // [h][d][m], single fp16
__device__ __half g_Xhi[(size_t)SEQL * NMODEL];
__device__ __half g_Xlo[(size_t)SEQL * NMODEL];
__device__ __half g_Whi[3][(size_t)NMODEL * NMODEL];       // transposed: [n][k]
__device__ __half g_Wlo[3][(size_t)NMODEL * NMODEL];

// ======================= 0a) split cache_K (scaled by LOG2E) =======================
__global__ void convert_cacheK(const float4* __restrict__ cK) {
    const int n = HEADS * MCACHE * DHEAD / 4;
    __half2* Hi = reinterpret_cast<__half2*>(g_Khi);
    __half2* Lo = reinterpret_cast<__half2*>(g_Klo);
    for (int i = blockIdx.x * blockDim.x + threadIdx.x; i < n;
         i += gridDim.x * blockDim.x) {
        float4 v = cK[i];
        v.x *= LOG2E; v.y *= LOG2E; v.z *= LOG2E; v.w *= LOG2E;
        const uint32_t h0 = packh2(v.x, v.y);
        const uint32_t h1 = packh2(v.z, v.w);
        const float2 f0 = h2f2(h0), f1 = h2f2(h1);
        Hi[2 * i]     = *reinterpret_cast<const __half2*>(&h0);
        Hi[2 * i + 1] = *reinterpret_cast<const __half2*>(&h1);
        const uint32_t l0 = packh2(v.x - f0.x, v.y - f0.y);
        const uint32_t l1 = packh2(v.z - f1.x, v.w - f1.y);
        Lo[2 * i]     = *reinterpret_cast<const __half2*>(&l0);
        Lo[2 * i + 1] = *reinterpret_cast<const __half2*>(&l1);
    }
}

// ======================= 0b) transpose cache_V -> fp16 (half2 stores) ==========
__global__ void __launch_bounds__(256)
convert_cacheV(const float* __restrict__ cV) {
    __shared__ float tile[32][33];
    const int h  = blockIdx.z;
    const int m0 = blockIdx.x * 32;
    const int d0 = blockIdx.y * 32;
    const int t = threadIdx.x;
    const int tx = t & 31, ty = t >> 5;
#pragma unroll
    for (int i = 0; i < 4; i++)
        tile[ty + 8 * i][tx] =
            cV[((size_t)h * MCACHE + m0 + ty + 8 * i) * DHEAD + d0 + tx];
    __syncthreads();
    const int kp = t & 15;          // m pair index (0..15)
    const int dl0 = t >> 4;         // d_local (0..15)
#pragma unroll
    for (int j = 0; j < 2; j++) {
        const int dl = dl0 + 16 * j;
        const float v0 = tile[2 * kp][dl];
        const float v1 = tile[2 * kp + 1][dl];
        const uint32_t hv = packh2(v0, v1);
        const size_t o2 = (((size_t)h * DHEAD + d0 + dl) * MCACHE + m0) / 2 + kp;
        reinterpret_cast<uint32_t*>(g_Vt)[o2] = hv;
    }
}

// ======================= 0c) split X =======================
__global__ void convert_X_kernel(const float4* __restrict__ X) {
    const int n = SEQL * NMODEL / 4;
    __half2* Hi = reinterpret_cast<__half2*>(g_Xhi);
    __half2* Lo = reinterpret_cast<__half2*>(g_Xlo);
    for (int i = blockIdx.x * blockDim.x + threadIdx.x; i < n;
         i += gridDim.x * blockDim.x) {
        const float4 v = X[i];
        const uint32_t h0 = packh2(v.x, v.y);
        const uint32_t h1 = packh2(v.z, v.w);
        const float2 f0 = h2f2(h0), f1 = h2f2(h1);
        Hi[2 * i]     = *reinterpret_cast<const __half2*>(&h0);
        Hi[2 * i + 1] = *reinterpret_cast<const __half2*>(&h1);
        const uint32_t l0 = packh2(v.x - f0.x, v.y - f0.y);
        const uint32_t l1 = packh2(v.z - f1.x, v.w - f1.y);
        Lo[2 * i]     = *reinterpret_cast<const __half2*>(&l0);
        Lo[2 * i + 1] = *reinterpret_cast<const __half2*>(&l1);
    }
}

// ======================= 0d) transpose + split W (half2 stores) ==============
__global__ void __launch_bounds__(256)
convert_W_kernel(const float* __restrict__ Wq,
                 const float* __restrict__ Wk,
                 const float* __restrict__ Wv) {
    __shared__ float tile[32][33];   // [k][n]
    const int z = blockIdx.z;
    const float* __restrict__ W = (z == 0) ? Wq : ((z == 1) ? Wk : Wv);
    const int n0 = blockIdx.x * 32;
    const int k0 = blockIdx.y * 32;
    const int t = threadIdx.x;
    const int tx = t & 31, ty = t >> 5;
#pragma unroll
    for (int i = 0; i < 4; i++)
        tile[ty + 8 * i][tx] = W[(size_t)(k0 + ty + 8 * i) * NMODEL + n0 + tx];
    __syncthreads();
    uint32_t* Hi2 = reinterpret_cast<uint32_t*>(g_Whi[z]);
    uint32_t* Lo2 = reinterpret_cast<uint32_t*>(g_Wlo[z]);
    const int kp  = t & 15;          // k pair (0..15)
    const int nl0 = t >> 4;          // n_local (0..15)
#pragma unroll
    for (int j = 0; j < 2; j++) {
        const int nl = nl0 + 16 * j;
        const float v0 = tile[2 * kp][nl];
        const float v1 = tile[2 * kp + 1][nl];
        const uint32_t hi = packh2(v0, v1);
        const float2 f = h2f2(hi);
        const uint32_t lo = packh2(v0 - f.x, v1 - f.y);
        const size_t o2 = ((size_t)(n0 + nl) * NMODEL + k0) / 2 + kp;
        Hi2[o2] = hi;
        Lo2[o2] = lo;
    }
}

// ======================= 1) split-fp16 mma.sync QKV GEMM (R9/R11 winner) ============
#define GBM 128
#define GBN 128
#define GBK 32
#define G_ITERS (NMODEL / GBK)
#define G_STAGE 32768                 // Ahi8K | Alo8K | Bhi8K | Blo8K
#define G_SMEM  (3 * G_STAGE)         // 98304; x2 CTAs = 192KB <= 228KB

// smem chunk swizzle for 64B rows (4 chunks of 16B)
#define SWZ(row, ch) ((uint32_t)((row) * 64 + ((((ch) ^ (((row) >> 1) & 3))) << 4)))
// fp32 staging swizzle (128 floats per row, 128 rows)
#define SWZ4(m, d) ((uint32_t)((m) * 128 + ((d) ^ ((m) & 31))))

__global__ void __launch_bounds__(256, 2)
qkv_gemm_mma(const int* __restrict__ Pp) {
    extern __shared__ char smg[];
    const uint32_t sb = smem_to_u32(smg);
    const int t = threadIdx.x, lane = t & 31, wid = t >> 5;
    const int mt = blockIdx.x;   // consecutive bids share the same W slab (L2 reuse)
    const int nt = blockIdx.y;
    const int z  = blockIdx.z;
    const int wm = wid & 1;
    const int wn = wid >> 1;
    const bool full = (z != 2);  // V projection drops the Xlo*Whi MMA (and Alo loads)

    const __half* __restrict__ Ah = g_Xhi + (size_t)(mt * GBM) * NMODEL;
    const __half* __restrict__ Al = g_Xlo + (size_t)(mt * GBM) * NMODEL;
    const __half* __restrict__ Bh = g_Whi[z] + (size_t)(nt * GBN) * NMODEL;
    const __half* __restrict__ Bl = g_Wlo[z] + (size_t)(nt * GBN) * NMODEL;

    float acc[4][4][4];
#pragma unroll
    for (int i = 0; i < 4; i++)
#pragma unroll
        for (int j = 0; j < 4; j++)
#pragma unroll
            for (int r = 0; r < 4; r++) acc[i][j][r] = 0.f;

    const int r0 = t >> 2, c0 = t & 3;
    const int r1 = (t + 256) >> 2, c1 = t & 3;

#define G_ISSUE(slot, k0)                                                      \
    do {                                                                       \
        const uint32_t stg = sb + (uint32_t)(slot) * G_STAGE;                  \
        const size_t ga0 = (size_t)r0 * NMODEL + (k0) + c0 * 8;                \
        const size_t ga1 = (size_t)r1 * NMODEL + (k0) + c1 * 8;                \
        cpasync16(stg + SWZ(r0, c0), Ah + ga0);                                \
        cpasync16(stg + SWZ(r1, c1), Ah + ga1);                                \
        if (full) {                                                            \
            cpasync16(stg + 8192 + SWZ(r0, c0), Al + ga0);                     \
            cpasync16(stg + 8192 + SWZ(r1, c1), Al + ga1);                     \
        }                                                                      \
        cpasync16(stg + 16384 + SWZ(r0, c0), Bh + ga0);                        \
        cpasync16(stg + 16384 + SWZ(r1, c1), Bh + ga1);                        \
        cpasync16(stg + 24576 + SWZ(r0, c0), Bl + ga0);                        \
        cpasync16(stg + 24576 + SWZ(r1, c1), Bl + ga1);                        \
        CP_COMMIT();                                                           \
    } while (0)

    // prologue: stages 0, 1
    G_ISSUE(0, 0);
    G_ISSUE(1, GBK);

    const int rowA = wm * 64 + (lane & 7) + ((lane >> 3) & 1) * 8;
    const int chA  = (lane >> 4);
    const int rowB = wn * 32 + (lane & 7) + ((lane & 16) ? 8 : 0);
    const int chB  = ((lane >> 3) & 1);

    int slot = 0, nslot = 2;
    for (int c = 0; c < G_ITERS; ++c) {
        if (c + 2 < G_ITERS) { CP_WAIT(1); } else { CP_WAIT(0); }
        __syncthreads();
        if (c + 2 < G_ITERS) {
            G_ISSUE(nslot, (c + 2) * GBK);
        }

        const uint32_t sA = sb + (uint32_t)slot * G_STAGE;
        const uint32_t sB = sA + 16384;
#pragma unroll
        for (int g = 0; g < 2; ++g) {
            uint32_t bh[2][4], bl[2][4];
#pragma unroll
            for (int bj = 0; bj < 2; ++bj) {
                const uint32_t ad = sB + SWZ(rowB + bj * 16, 2 * g + chB);
                ldmat4(bh[bj], ad);
                ldmat4(bl[bj], ad + 8192);
            }
#pragma unroll
            for (int mi = 0; mi < 4; ++mi) {
                uint32_t ah[4], al[4];
                const uint32_t ad = sA + SWZ(rowA + mi * 16, 2 * g + chA);
                ldmat4(ah, ad);
                if (full) ldmat4(al, ad + 8192);
#pragma unroll
                for (int nj = 0; nj < 4; ++nj) {
                    const uint32_t* bhp = &bh[nj >> 1][(nj & 1) * 2];
                    const uint32_t* blp = &bl[nj >> 1][(nj & 1) * 2];
                    mma_f16(acc[mi][nj], ah, bhp);
                    mma_f16(acc[mi][nj], ah, blp);
                    if (full) mma_f16(acc[mi][nj], al, bhp);
                }
            }
        }
        slot  = (slot == 2) ? 0 : slot + 1;
        nslot = (nslot == 2) ? 0 : nslot + 1;
    }
#undef G_ISSUE

    // ---- epilogue ----
    const int P = *Pp;
    const int qr = lane >> 2, qc = (lane & 3) * 2;

    if (z != 2) {
        const float scl = (z == 1) ? LOG2E : 1.f;  // K pre-scaled for exp2 softmax
        __half* Dhi = (z == 0) ? g_Qhi : g_Khi;
        __half* Dlo = (z == 0) ? g_Qlo : g_Klo;
        const int rows  = (z == 0) ? SEQL : MCACHE;
        const int rbase = (z == 0) ? 0 : P;
#pragma unroll
        for (int mi = 0; mi < 4; ++mi)
#pragma unroll
            for (int nj = 0; nj < 4; ++nj) {
                const int m0 = mt * GBM + wm * 64 + mi * 16 + qr;
                const int n  = nt * GBN + wn * 32 + nj * 8 + qc;
                const int h = n >> 7, d0 = n & 127;
#pragma unroll
                for (int hv = 0; hv < 2; ++hv) {
                    const float v0 = acc[mi][nj][2 * hv] * scl;
                    const float v1 = acc[mi][nj][2 * hv + 1] * scl;
                    const uint32_t hi = packh2(v0, v1);
                    const float2 f = h2f2(hi);
                    const uint32_t lo = packh2(v0 - f.x, v1 - f.y);
                    const size_t o = ((size_t)h * rows + rbase + m0 + 8 * hv) * DHEAD + d0;
                    *reinterpret_cast<uint32_t*>(Dhi + o) = hi;
                    *reinterpret_cast<uint32_t*>(Dlo + o) = lo;
                }
            }
    } else {
        // V: stage fp32 tile in smem, transpose to g_Vt[h=nt][d][m] as fp16
        float* st = reinterpret_cast<float*>(smg);
        __syncthreads();  // all warps out of the MMA loop before smem reuse
#pragma unroll
        for (int mi = 0; mi < 4; ++mi)
#pragma unroll
            for (int nj = 0; nj < 4; ++nj) {
                const int ml = wm * 64 + mi * 16 + qr;
                const int nl = wn * 32 + nj * 8 + qc;
                st[SWZ4(ml, nl)]         = acc[mi][nj][0];
                st[SWZ4(ml, nl + 1)]     = acc[mi][nj][1];
                st[SWZ4(ml + 8, nl)]     = acc[mi][nj][2];
                st[SWZ4(ml + 8, nl + 1)] = acc[mi][nj][3];
            }
        __syncthreads();
        const int d  = t >> 1;
        const int ms = (t & 1) * 64;
        const size_t ob = ((size_t)nt * DHEAD + d) * MCACHE + P + mt * GBM + ms;
#pragma unroll
        for (int mm = 0; mm < 64; mm += 2) {
            const uint32_t hv = packh2(st[SWZ4(ms + mm, d)], st[SWZ4(ms + mm + 1, d)]);
            *reinterpret_cast<uint32_t*>(g_Vt + ob + mm) = hv;
        }
    }
}

// ======================= 2) tensor-core flash attention (fp16, R11 winner + skip) =====
// CTA: 128 q x 1 head, 8 warps x 16 q rows. QK^T: 3-MMA split. PV: single-MMA
// (fp16 P-hat, fp16 V). Base-2 softmax. O-rescale skipped when no new max
// (corr == 1.0 exactly — bit-identical fast path).
#define ABQ   128
#define ABKV  128
#define NKT   (MCACHE / ABKV)   // 32
#define SWB(row, ch) ((uint32_t)((row) * 256 + ((((ch) ^ ((row) & 7))) << 4)))
#define AQ_HI 0
#define AQ_LO 32768
#define AK_HI 65536
#define AK_LO 98304
#define AV    131072
#define A_SMEM 163840

__device__ __forceinline__ void issue_pair(uint32_t smhi, uint32_t smlo,
                                           const __half* ghi, const __half* glo,
                                           size_t rowstride, int t) {
#pragma unroll
    for (int i = 0; i < 8; ++i) {
        const int idx = t + i * 256;
        const int row = idx >> 4, ch = idx & 15;
        const size_t go = (size_t)row * rowstride + ch * 8;
        const uint32_t so = SWB(row, ch);
        cpasync16(smhi + so, ghi + go);
        cpasync16(smlo + so, glo + go);
    }
}
__device__ __forceinline__ void issue_single(uint32_t sm, const __half* g,
                                             size_t rowstride, int t) {
#pragma unroll
    for (int i = 0; i < 8; ++i) {
        const int idx = t + i * 256;
        const int row = idx >> 4, ch = idx & 15;
        cpasync16(sm + SWB(row, ch), g + (size_t)row * rowstride + ch * 8);
    }
}

__global__ void __launch_bounds__(256, 1)
attn_tc(float* __restrict__ out) {
    extern __shared__ char sma[];
    const uint32_t sb = smem_to_u32(sma);
    const int t = threadIdx.x, lane = t & 31, wid = t >> 5;
    const int h  = blockIdx.y;
    const int q0 = blockIdx.x * ABQ;
    const int q0w = wid * 16;

    const __half* __restrict__ Qh = g_Qhi + ((size_t)h * SEQL + q0) * DHEAD;
    const __half* __restrict__ Ql = g_Qlo + ((size_t)h * SEQL + q0) * DHEAD;
    const __half* __restrict__ Kh = g_Khi + (size_t)h * MCACHE * DHEAD;
    const __half* __restrict__ Kl = g_Klo + (size_t)h * MCACHE * DHEAD;
    const __half* __restrict__ Vt = g_Vt + (size_t)h * DHEAD * MCACHE;

    issue_pair(sb + AQ_HI, sb + AQ_LO, Qh, Ql, DHEAD, t);
    issue_pair(sb + AK_HI, sb + AK_LO, Kh, Kl, DHEAD, t);
    CP_COMMIT();
    issue_single(sb + AV, Vt, MCACHE, t);
    CP_COMMIT();
    CP_WAIT(1);
    __syncthreads();

    const int rowA = (lane & 7) + ((lane >> 3) & 1) * 8;
    const int chA  = (lane >> 4);
    const int rowB = (lane & 7) + ((lane & 16) ? 8 : 0);
    const int chB  = ((lane >> 3) & 1);

    float m0 = -1e30f, m1 = -1e30f, l0 = 0.f, l1 = 0.f;
    float o[16][4];
#pragma unroll
    for (int i = 0; i < 16; i++)
#pragma unroll
        for (int r = 0; r < 4; r++) o[i][r] = 0.f;

    for (int kt = 0; kt < NKT; ++kt) {
        // ---- S = Q K^T (split-fp16, 3 MMA; scores in log2-domain) ----
        float s[16][4];
#pragma unroll
        for (int i = 0; i < 16; i++)
#pragma unroll
            for (int r = 0; r < 4; r++) s[i][r] = 0.f;

#pragma unroll
        for (int ks = 0; ks < 8; ++ks) {
            uint32_t ah[4], al[4];
            const uint32_t qa = sb + SWB(q0w + rowA, 2 * ks + chA);
            ldmat4(ah, qa + AQ_HI);
            ldmat4(al, qa + AQ_LO);
#pragma unroll
            for (int bj = 0; bj < 8; ++bj) {
                uint32_t bh[4], bl[4];
                const uint32_t ka = sb + SWB(bj * 16 + rowB, 2 * ks + chB);
                ldmat4(bh, ka + AK_HI);
                ldmat4(bl, ka + AK_LO);
                mma_f16(s[2 * bj],     ah, &bh[0]);
                mma_f16(s[2 * bj + 1], ah, &bh[2]);
                mma_f16(s[2 * bj],     ah, &bl[0]);
                mma_f16(s[2 * bj + 1], ah, &bl[2]);
                mma_f16(s[2 * bj],     al, &bh[0]);
                mma_f16(s[2 * bj + 1], al, &bh[2]);
            }
        }
        __syncthreads();
        if (kt + 1 < NKT) {
            issue_pair(sb + AK_HI, sb + AK_LO,
                       Kh + (size_t)(kt + 1) * ABKV * DHEAD,
                       Kl + (size_t)(kt + 1) * ABKV * DHEAD, DHEAD, t);
            CP_COMMIT();
        }

        // ---- online softmax (base-2, MUFU); round P through fp16 ----
        float tm0 = s[0][0], tm1 = s[0][2];
#pragma unroll
        for (int nj = 0; nj < 16; ++nj) {
            tm0 = fmaxf(tm0, fmaxf(s[nj][0], s[nj][1]));
            tm1 = fmaxf(tm1, fmaxf(s[nj][2], s[nj][3]));
        }
        tm0 = fmaxf(tm0, __shfl_xor_sync(0xffffffffu, tm0, 1));
        tm0 = fmaxf(tm0, __shfl_xor_sync(0xffffffffu, tm0, 2));
        tm1 = fmaxf(tm1, __shfl_xor_sync(0xffffffffu, tm1, 1));
        tm1 = fmaxf(tm1, __shfl_xor_sync(0xffffffffu, tm1, 2));
        const float nm0 = fmaxf(m0, tm0), nm1 = fmaxf(m1, tm1);
        const bool newmax = (nm0 != m0) | (nm1 != m1);
        float sum0 = 0.f, sum1 = 0.f;
#pragma unroll
        for (int nj = 0; nj < 16; ++nj) {
            const uint32_t p01 = packh2(ex2f(s[nj][0] - nm0), ex2f(s[nj][1] - nm0));
            const uint32_t p23 = packh2(ex2f(s[nj][2] - nm1), ex2f(s[nj][3] - nm1));
            const float2 f01 = h2f2(p01), f23 = h2f2(p23);
            s[nj][0] = f01.x; s[nj][1] = f01.y;
            s[nj][2] = f23.x; s[nj][3] = f23.y;
            sum0 += f01.x + f01.y;
            sum1 += f23.x + f23.y;
        }
        sum0 += __shfl_xor_sync(0xffffffffu, sum0, 1);
        sum0 += __shfl_xor_sync(0xffffffffu, sum0, 2);
        sum1 += __shfl_xor_sync(0xffffffffu, sum1, 1);
        sum1 += __shfl_xor_sync(0xffffffffu, sum1, 2);
        if (newmax) {
            // corr != 1 only when a new max appeared (exact fast path otherwise)
            const float cr0 = ex2f(m0 - nm0), cr1 = ex2f(m1 - nm1);
            l0 = l0 * cr0 + sum0;
            l1 = l1 * cr1 + sum1;
            m0 = nm0; m1 = nm1;
#pragma unroll
            for (int nj = 0; nj < 16; ++nj) {
                o[nj][0] *= cr0; o[nj][1] *= cr0;
                o[nj][2] *= cr1; o[nj][3] *= cr1;
            }
        } else {
            l0 += sum0;
            l1 += sum1;
        }

        // ---- O += P V (single-MMA: fp16 P-hat x fp16 V) ----
        CP_WAIT(1);
        __syncthreads();

#pragma unroll
        for (int j = 0; j < 8; ++j) {
            uint32_t ap[4];
            ap[0] = packh2(s[2 * j][0],     s[2 * j][1]);
            ap[1] = packh2(s[2 * j][2],     s[2 * j][3]);
            ap[2] = packh2(s[2 * j + 1][0], s[2 * j + 1][1]);
            ap[3] = packh2(s[2 * j + 1][2], s[2 * j + 1][3]);
#pragma unroll
            for (int bj = 0; bj < 8; ++bj) {
                uint32_t vh[4];
                ldmat4(vh, sb + AV + SWB(bj * 16 + rowB, 2 * j + chB));
                mma_f16(o[2 * bj],     ap, &vh[0]);
                mma_f16(o[2 * bj + 1], ap, &vh[2]);
            }
        }
        __syncthreads();
        if (kt + 1 < NKT) {
            issue_single(sb + AV, Vt + (size_t)(kt + 1) * ABKV, MCACHE, t);
            CP_COMMIT();
            CP_WAIT(1);
            __syncthreads();
        }
    }

    // ---- normalize + write ----
    const float inv0 = __fdividef(1.f, l0);
    const float inv1 = __fdividef(1.f, l1);
    const int row0 = q0 + q0w + (lane >> 2);
    const int qc = (lane & 3) * 2;
#pragma unroll
    for (int nj = 0; nj < 16; ++nj) {
        const int d0 = nj * 8 + qc;
        float* p0 = out + ((size_t)h * SEQL + row0) * DHEAD + d0;
        float* p1 = out + ((size_t)h * SEQL + row0 + 8) * DHEAD + d0;
        *reinterpret_cast<float2*>(p0) = make_float2(o[nj][0] * inv0, o[nj][1] * inv0);
        *reinterpret_cast<float2*>(p1) = make_float2(o[nj][2] * inv1, o[nj][3] * inv1);
    }
}

// ======================= launch =======================
extern "C" void kernel_launch(void* const* d_in, const int* in_sizes, int n_in,
                              void* d_out, int out_size) {
    const float* X  = (const float*)d_in[0];
    const float* Wq = (const float*)d_in[1];
    const float* Wk = (const float*)d_in[2];
    const float* Wv = (const float*)d_in[3];
    const float* cK = (const float*)d_in[4];
    const float* cV = (const float*)d_in[5];
    const int*   Pp = (const int*)d_in[6];

    convert_cacheK<<<1024, 256>>>((const float4*)cK);
    dim3 vgrid(MCACHE / 32, DHEAD / 32, HEADS);
    convert_cacheV<<<vgrid, 256>>>(cV);
    convert_X_kernel<<<2048, 256>>>((const float4*)X);
    dim3 wgrid(NMODEL / 32, NMODEL / 32, 3);
    convert_W_kernel<<<wgrid, 256>>>(Wq, Wk, Wv);

    cudaFuncSetAttribute(qkv_gemm_mma, cudaFuncAttributeMaxDynamicSharedMemorySize,
                         G_SMEM);
    dim3 ggrid(SEQL / GBM, NMODEL / GBN, 3);
    qkv_gemm_mma<<<ggrid, 256, G_SMEM>>>(Pp);

    cudaFuncSetAttribute(attn_tc, cudaFuncAttributeMaxDynamicSharedMemorySize,
                         A_SMEM);
    dim3 agrid(SEQL / ABQ, HEADS);
    attn_tc<<<agrid, 256, A_SMEM>>>((float*)d_out);
}

// round 14
// speedup vs baseline: 1.0491x; 1.0491x over previous
#include <cuda_runtime.h>
#include <cuda_fp16.h>
#include <cstdint>

// Problem dims (fixed by the reference)
#define SEQL   2048
#define NMODEL 4096
#define HEADS  32
#define DHEAD  128
#define MCACHE 4096
#define LOG2E  1.4426950408889634f
#define KVSPLIT 2
#define MSPLIT (MCACHE / KVSPLIT)

// ======================= family-portable PTX helpers =======================
__device__ __forceinline__ uint32_t smem_to_u32(const void* p) {
    uint32_t a;
    asm("{ .reg .u64 t; cvta.to.shared.u64 t, %1; cvt.u32.u64 %0, t; }"
        : "=r"(a) : "l"(p));
    return a;
}
__device__ __forceinline__ void mma_f16(float* c, const uint32_t* a, const uint32_t* b) {
    asm volatile(
        "mma.sync.aligned.m16n8k16.row.col.f32.f16.f16.f32 "
        "{%0,%1,%2,%3}, {%4,%5,%6,%7}, {%8,%9}, {%0,%1,%2,%3};"
        : "+f"(c[0]), "+f"(c[1]), "+f"(c[2]), "+f"(c[3])
        : "r"(a[0]), "r"(a[1]), "r"(a[2]), "r"(a[3]), "r"(b[0]), "r"(b[1]));
}
__device__ __forceinline__ void ldmat4(uint32_t* r, uint32_t addr) {
    asm volatile("ldmatrix.sync.aligned.m8n8.x4.shared.b16 {%0,%1,%2,%3}, [%4];"
        : "=r"(r[0]), "=r"(r[1]), "=r"(r[2]), "=r"(r[3]) : "r"(addr));
}
__device__ __forceinline__ void cpasync16(uint32_t dst, const void* src) {
    asm volatile("cp.async.cg.shared.global [%0], [%1], 16;" :: "r"(dst), "l"(src));
}
#define CP_COMMIT() asm volatile("cp.async.commit_group;" ::: "memory")
#define CP_WAIT(n)  asm volatile("cp.async.wait_group %0;" :: "n"(n) : "memory")

// pack two f32 -> f16x2 register (low half = first arg)
__device__ __forceinline__ uint32_t packh2(float lo, float hi) {
    uint32_t r;
    asm("cvt.rn.f16x2.f32 %0, %1, %2;" : "=r"(r) : "f"(hi), "f"(lo));
    return r;
}
__device__ __forceinline__ float2 h2f2(uint32_t u) {
    __half2 h = *reinterpret_cast<__half2*>(&u);
    return __half22float2(h);
}
// MUFU.EX2 (base-2 exp, approx: 2^-22 rel err)
__device__ __forceinline__ float ex2f(float x) {
    float y;
    asm("ex2.approx.f32 %0, %1;" : "=f"(y) : "f"(x));
    return y;
}

// ======================= scratch (device globals) =======================
__device__ __half g_Qhi[(size_t)HEADS * SEQL * DHEAD];
__device__ __half g_Qlo[(size_t)HEADS * SEQL * DHEAD];
__device__ __half g_Khi[(size_t)HEADS * MCACHE * DHEAD];   // pre-scaled by LOG2E
__device__ __half g_Klo[(size_t)HEADS * MCACHE * DHEAD];
__device__ __half g_Vt[(size_t)HEADS * DHEAD * MCACHE];    // [h][d][m], single fp16
__device__ __half g_Xhi[(size_t)SEQL * NMODEL];
__device__ __half g_Xlo[(size_t)SEQL * NMODEL];
__device__ __half g_Whi[3][(size_t)NMODEL * NMODEL];       // transposed: [n][k]
__device__ __half g_Wlo[3][(size_t)NMODEL * NMODEL];
// split-KV partials
__device__ float g_Op[KVSPLIT][(size_t)HEADS * SEQL * DHEAD];  // unnormalized O
__device__ float g_Pm[KVSPLIT][(size_t)HEADS * SEQL];          // row max (log2 dom.)
__device__ float g_Pl[KVSPLIT][(size_t)HEADS * SEQL];          // row sum

// ======================= 0a) split cache_K (scaled by LOG2E) =======================
__global__ void convert_cacheK(const float4* __restrict__ cK) {
    const int n = HEADS * MCACHE * DHEAD / 4;
    __half2* Hi = reinterpret_cast<__half2*>(g_Khi);
    __half2* Lo = reinterpret_cast<__half2*>(g_Klo);
    for (int i = blockIdx.x * blockDim.x + threadIdx.x; i < n;
         i += gridDim.x * blockDim.x) {
        float4 v = cK[i];
        v.x *= LOG2E; v.y *= LOG2E; v.z *= LOG2E; v.w *= LOG2E;
        const uint32_t h0 = packh2(v.x, v.y);
        const uint32_t h1 = packh2(v.z, v.w);
        const float2 f0 = h2f2(h0), f1 = h2f2(h1);
        Hi[2 * i]     = *reinterpret_cast<const __half2*>(&h0);
        Hi[2 * i + 1] = *reinterpret_cast<const __half2*>(&h1);
        const uint32_t l0 = packh2(v.x - f0.x, v.y - f0.y);
        const uint32_t l1 = packh2(v.z - f1.x, v.w - f1.y);
        Lo[2 * i]     = *reinterpret_cast<const __half2*>(&l0);
        Lo[2 * i + 1] = *reinterpret_cast<const __half2*>(&l1);
    }
}

// ======================= 0b) transpose cache_V -> fp16 (half2 stores) ==========
__global__ void __launch_bounds__(256)
convert_cacheV(const float* __restrict__ cV) {
    __shared__ float tile[32][33];
    const int h  = blockIdx.z;
    const int m0 = blockIdx.x * 32;
    const int d0 = blockIdx.y * 32;
    const int t = threadIdx.x;
    const int tx = t & 31, ty = t >> 5;
#pragma unroll
    for (int i = 0; i < 4; i++)
        tile[ty + 8 * i][tx] =
            cV[((size_t)h * MCACHE + m0 + ty + 8 * i) * DHEAD + d0 + tx];
    __syncthreads();
    const int kp = t & 15;
    const int dl0 = t >> 4;
#pragma unroll
    for (int j = 0; j < 2; j++) {
        const int dl = dl0 + 16 * j;
        const float v0 = tile[2 * kp][dl];
        const float v1 = tile[2 * kp + 1][dl];
        const uint32_t hv = packh2(v0, v1);
        const size_t o2 = (((size_t)h * DHEAD + d0 + dl) * MCACHE + m0) / 2 + kp;
        reinterpret_cast<uint32_t*>(g_Vt)[o2] = hv;
    }
}

// ======================= 0c) split X =======================
__global__ void convert_X_kernel(const float4* __restrict__ X) {
    const int n = SEQL * NMODEL / 4;
    __half2* Hi = reinterpret_cast<__half2*>(g_Xhi);
    __half2* Lo = reinterpret_cast<__half2*>(g_Xlo);
    for (int i = blockIdx.x * blockDim.x + threadIdx.x; i < n;
         i += gridDim.x * blockDim.x) {
        const float4 v = X[i];
        const uint32_t h0 = packh2(v.x, v.y);
        const uint32_t h1 = packh2(v.z, v.w);
        const float2 f0 = h2f2(h0), f1 = h2f2(h1);
        Hi[2 * i]     = *reinterpret_cast<const __half2*>(&h0);
        Hi[2 * i + 1] = *reinterpret_cast<const __half2*>(&h1);
        const uint32_t l0 = packh2(v.x - f0.x, v.y - f0.y);
        const uint32_t l1 = packh2(v.z - f1.x, v.w - f1.y);
        Lo[2 * i]     = *reinterpret_cast<const __half2*>(&l0);
        Lo[2 * i + 1] = *reinterpret_cast<const __half2*>(&l1);
    }
}

// ======================= 0d) transpose + split W (half2 stores) ==============
__global__ void __launch_bounds__(256)
convert_W_kernel(const float* __restrict__ Wq,
                 const float* __restrict__ Wk,
                 const float* __restrict__ Wv) {
    __shared__ float tile[32][33];   // [k][n]
    const int z = blockIdx.z;
    const float* __restrict__ W = (z == 0) ? Wq : ((z == 1) ? Wk : Wv);
    const int n0 = blockIdx.x * 32;
    const int k0 = blockIdx.y * 32;
    const int t = threadIdx.x;
    const int tx = t & 31, ty = t >> 5;
#pragma unroll
    for (int i = 0; i < 4; i++)
        tile[ty + 8 * i][tx] = W[(size_t)(k0 + ty + 8 * i) * NMODEL + n0 + tx];
    __syncthreads();
    uint32_t* Hi2 = reinterpret_cast<uint32_t*>(g_Whi[z]);
    uint32_t* Lo2 = reinterpret_cast<uint32_t*>(g_Wlo[z]);
    const int kp  = t & 15;
    const int nl0 = t >> 4;
#pragma unroll
    for (int j = 0; j < 2; j++) {
        const int nl = nl0 + 16 * j;
        const float v0 = tile[2 * kp][nl];
        const float v1 = tile[2 * kp + 1][nl];
        const uint32_t hi = packh2(v0, v1);
        const float2 f = h2f2(hi);
        const uint32_t lo = packh2(v0 - f.x, v1 - f.y);
        const size_t o2 = ((size_t)(n0 + nl) * NMODEL + k0) / 2 + kp;
        Hi2[o2] = hi;
        Lo2[o2] = lo;
    }
}

// ======================= 1) split-fp16 mma.sync QKV GEMM (R9/R11 winner) ============
#define GBM 128
#define GBN 128
#define GBK 32
#define G_ITERS (NMODEL / GBK)
#define G_STAGE 32768
#define G_SMEM  (3 * G_STAGE)

#define SWZ(row, ch) ((uint32_t)((row) * 64 + ((((ch) ^ (((row) >> 1) & 3))) << 4)))
#define SWZ4(m, d) ((uint32_t)((m) * 128 + ((d) ^ ((m) & 31))))

__global__ void __launch_bounds__(256, 2)
qkv_gemm_mma(const int* __restrict__ Pp) {
    extern __shared__ char smg[];
    const uint32_t sb = smem_to_u32(smg);
    const int t = threadIdx.x, lane = t & 31, wid = t >> 5;
    const int mt = blockIdx.x;
    const int nt = blockIdx.y;
    const int z  = blockIdx.z;
    const int wm = wid & 1;
    const int wn = wid >> 1;
    const bool full = (z != 2);

    const __half* __restrict__ Ah = g_Xhi + (size_t)(mt * GBM) * NMODEL;
    const __half* __restrict__ Al = g_Xlo + (size_t)(mt * GBM) * NMODEL;
    const __half* __restrict__ Bh = g_Whi[z] + (size_t)(nt * GBN) * NMODEL;
    const __half* __restrict__ Bl = g_Wlo[z] + (size_t)(nt * GBN) * NMODEL;

    float acc[4][4][4];
#pragma unroll
    for (int i = 0; i < 4; i++)
#pragma unroll
        for (int j = 0; j < 4; j++)
#pragma unroll
            for (int r = 0; r < 4; r++) acc[i][j][r] = 0.f;

    const int r0 = t >> 2, c0 = t & 3;
    const int r1 = (t + 256) >> 2, c1 = t & 3;

#define G_ISSUE(slot, k0)                                                      \
    do {                                                                       \
        const uint32_t stg = sb + (uint32_t)(slot) * G_STAGE;                  \
        const size_t ga0 = (size_t)r0 * NMODEL + (k0) + c0 * 8;                \
        const size_t ga1 = (size_t)r1 * NMODEL + (k0) + c1 * 8;                \
        cpasync16(stg + SWZ(r0, c0), Ah + ga0);                                \
        cpasync16(stg + SWZ(r1, c1), Ah + ga1);                                \
        if (full) {                                                            \
            cpasync16(stg + 8192 + SWZ(r0, c0), Al + ga0);                     \
            cpasync16(stg + 8192 + SWZ(r1, c1), Al + ga1);                     \
        }                                                                      \
        cpasync16(stg + 16384 + SWZ(r0, c0), Bh + ga0);                        \
        cpasync16(stg + 16384 + SWZ(r1, c1), Bh + ga1);                        \
        cpasync16(stg + 24576 + SWZ(r0, c0), Bl + ga0);                        \
        cpasync16(stg + 24576 + SWZ(r1, c1), Bl + ga1);                        \
        CP_COMMIT();                                                           \
    } while (0)

    G_ISSUE(0, 0);
    G_ISSUE(1, GBK);

    const int rowA = wm * 64 + (lane & 7) + ((lane >> 3) & 1) * 8;
    const int chA  = (lane >> 4);
    const int rowB = wn * 32 + (lane & 7) + ((lane & 16) ? 8 : 0);
    const int chB  = ((lane >> 3) & 1);

    int slot = 0, nslot = 2;
    for (int c = 0; c < G_ITERS; ++c) {
        if (c + 2 < G_ITERS) { CP_WAIT(1); } else { CP_WAIT(0); }
        __syncthreads();
        if (c + 2 < G_ITERS) {
            G_ISSUE(nslot, (c + 2) * GBK);
        }

        const uint32_t sA = sb + (uint32_t)slot * G_STAGE;
        const uint32_t sB = sA + 16384;
#pragma unroll
        for (int g = 0; g < 2; ++g) {
            uint32_t bh[2][4], bl[2][4];
#pragma unroll
            for (int bj = 0; bj < 2; ++bj) {
                const uint32_t ad = sB + SWZ(rowB + bj * 16, 2 * g + chB);
                ldmat4(bh[bj], ad);
                ldmat4(bl[bj], ad + 8192);
            }
#pragma unroll
            for (int mi = 0; mi < 4; ++mi) {
                uint32_t ah[4], al[4];
                const uint32_t ad = sA + SWZ(rowA + mi * 16, 2 * g + chA);
                ldmat4(ah, ad);
                if (full) ldmat4(al, ad + 8192);
#pragma unroll
                for (int nj = 0; nj < 4; ++nj) {
                    const uint32_t* bhp = &bh[nj >> 1][(nj & 1) * 2];
                    const uint32_t* blp = &bl[nj >> 1][(nj & 1) * 2];
                    mma_f16(acc[mi][nj], ah, bhp);
                    mma_f16(acc[mi][nj], ah, blp);
                    if (full) mma_f16(acc[mi][nj], al, bhp);
                }
            }
        }
        slot  = (slot == 2) ? 0 : slot + 1;
        nslot = (nslot == 2) ? 0 : nslot + 1;
    }
#undef G_ISSUE

    const int P = *Pp;
    const int qr = lane >> 2, qc = (lane & 3) * 2;

    if (z != 2) {
        const float scl = (z == 1) ? LOG2E : 1.f;
        __half* Dhi = (z == 0) ? g_Qhi : g_Khi;
        __half* Dlo = (z == 0) ? g_Qlo : g_Klo;
        const int rows  = (z == 0) ? SEQL : MCACHE;
        const int rbase = (z == 0) ? 0 : P;
#pragma unroll
        for (int mi = 0; mi < 4; ++mi)
#pragma unroll
            for (int nj = 0; nj < 4; ++nj) {
                const int m0 = mt * GBM + wm * 64 + mi * 16 + qr;
                const int n  = nt * GBN + wn * 32 + nj * 8 + qc;
                const int h = n >> 7, d0 = n & 127;
#pragma unroll
                for (int hv = 0; hv < 2; ++hv) {
                    const float v0 = acc[mi][nj][2 * hv] * scl;
                    const float v1 = acc[mi][nj][2 * hv + 1] * scl;
                    const uint32_t hi = packh2(v0, v1);
                    const float2 f = h2f2(hi);
                    const uint32_t lo = packh2(v0 - f.x, v1 - f.y);
                    const size_t o = ((size_t)h * rows + rbase + m0 + 8 * hv) * DHEAD + d0;
                    *reinterpret_cast<uint32_t*>(Dhi + o) = hi;
                    *reinterpret_cast<uint32_t*>(Dlo + o) = lo;
                }
            }
    } else {
        float* st = reinterpret_cast<float*>(smg);
        __syncthreads();
#pragma unroll
        for (int mi = 0; mi < 4; ++mi)
#pragma unroll
            for (int nj = 0; nj < 4; ++nj) {
                const int ml = wm * 64 + mi * 16 + qr;
                const int nl = wn * 32 + nj * 8 + qc;
                st[SWZ4(ml, nl)]         = acc[mi][nj][0];
                st[SWZ4(ml, nl + 1)]     = acc[mi][nj][1];
                st[SWZ4(ml + 8, nl)]     = acc[mi][nj][2];
                st[SWZ4(ml + 8, nl + 1)] = acc[mi][nj][3];
            }
        __syncthreads();
        const int d  = t >> 1;
        const int ms = (t & 1) * 64;
        const size_t ob = ((size_t)nt * DHEAD + d) * MCACHE + P + mt * GBM + ms;
#pragma unroll
        for (int mm = 0; mm < 64; mm += 2) {
            const uint32_t hv = packh2(st[SWZ4(ms + mm, d)], st[SWZ4(ms + mm + 1, d)]);
            *reinterpret_cast<uint32_t*>(g_Vt + ob + mm) = hv;
        }
    }
}

// ======================= 2) flash attention, split-KV (R11 core x 2 splits) ==========
// CTA: 128 q x 1 head x 1 kv-split (2048 cache rows, 16 tiles). Writes
// unnormalized partial O + per-row (m, l); combine kernel merges.
#define ABQ   128
#define ABKV  128
#define NKT_S (MSPLIT / ABKV)   // 16
#define SWB(row, ch) ((uint32_t)((row) * 256 + ((((ch) ^ ((row) & 7))) << 4)))
#define AQ_HI 0
#define AQ_LO 32768
#define AK_HI 65536
#define AK_LO 98304
#define AV    131072
#define A_SMEM 163840

__device__ __forceinline__ void issue_pair(uint32_t smhi, uint32_t smlo,
                                           const __half* ghi, const __half* glo,
                                           size_t rowstride, int t) {
#pragma unroll
    for (int i = 0; i < 8; ++i) {
        const int idx = t + i * 256;
        const int row = idx >> 4, ch = idx & 15;
        const size_t go = (size_t)row * rowstride + ch * 8;
        const uint32_t so = SWB(row, ch);
        cpasync16(smhi + so, ghi + go);
        cpasync16(smlo + so, glo + go);
    }
}
__device__ __forceinline__ void issue_single(uint32_t sm, const __half* g,
                                             size_t rowstride, int t) {
#pragma unroll
    for (int i = 0; i < 8; ++i) {
        const int idx = t + i * 256;
        const int row = idx >> 4, ch = idx & 15;
        cpasync16(sm + SWB(row, ch), g + (size_t)row * rowstride + ch * 8);
    }
}

__global__ void __launch_bounds__(256, 1)
attn_tc() {
    extern __shared__ char sma[];
    const uint32_t sb = smem_to_u32(sma);
    const int t = threadIdx.x, lane = t & 31, wid = t >> 5;
    const int h   = blockIdx.y;
    const int q0  = blockIdx.x * ABQ;
    const int kvs = blockIdx.z;
    const int q0w = wid * 16;

    const __half* __restrict__ Qh = g_Qhi + ((size_t)h * SEQL + q0) * DHEAD;
    const __half* __restrict__ Ql = g_Qlo + ((size_t)h * SEQL + q0) * DHEAD;
    const __half* __restrict__ Kh = g_Khi + ((size_t)h * MCACHE + kvs * MSPLIT) * DHEAD;
    const __half* __restrict__ Kl = g_Klo + ((size_t)h * MCACHE + kvs * MSPLIT) * DHEAD;
    const __half* __restrict__ Vt = g_Vt + (size_t)h * DHEAD * MCACHE + kvs * MSPLIT;

    issue_pair(sb + AQ_HI, sb + AQ_LO, Qh, Ql, DHEAD, t);
    issue_pair(sb + AK_HI, sb + AK_LO, Kh, Kl, DHEAD, t);
    CP_COMMIT();
    issue_single(sb + AV, Vt, MCACHE, t);
    CP_COMMIT();
    CP_WAIT(1);
    __syncthreads();

    const int rowA = (lane & 7) + ((lane >> 3) & 1) * 8;
    const int chA  = (lane >> 4);
    const int rowB = (lane & 7) + ((lane & 16) ? 8 : 0);
    const int chB  = ((lane >> 3) & 1);

    float m0 = -1e30f, m1 = -1e30f, l0 = 0.f, l1 = 0.f;
    float o[16][4];
#pragma unroll
    for (int i = 0; i < 16; i++)
#pragma unroll
        for (int r = 0; r < 4; r++) o[i][r] = 0.f;

    for (int kt = 0; kt < NKT_S; ++kt) {
        float s[16][4];
#pragma unroll
        for (int i = 0; i < 16; i++)
#pragma unroll
            for (int r = 0; r < 4; r++) s[i][r] = 0.f;

#pragma unroll
        for (int ks = 0; ks < 8; ++ks) {
            uint32_t ah[4], al[4];
            const uint32_t qa = sb + SWB(q0w + rowA, 2 * ks + chA);
            ldmat4(ah, qa + AQ_HI);
            ldmat4(al, qa + AQ_LO);
#pragma unroll
            for (int bj = 0; bj < 8; ++bj) {
                uint32_t bh[4], bl[4];
                const uint32_t ka = sb + SWB(bj * 16 + rowB, 2 * ks + chB);
                ldmat4(bh, ka + AK_HI);
                ldmat4(bl, ka + AK_LO);
                mma_f16(s[2 * bj],     ah, &bh[0]);
                mma_f16(s[2 * bj + 1], ah, &bh[2]);
                mma_f16(s[2 * bj],     ah, &bl[0]);
                mma_f16(s[2 * bj + 1], ah, &bl[2]);
                mma_f16(s[2 * bj],     al, &bh[0]);
                mma_f16(s[2 * bj + 1], al, &bh[2]);
            }
        }
        __syncthreads();
        if (kt + 1 < NKT_S) {
            issue_pair(sb + AK_HI, sb + AK_LO,
                       Kh + (size_t)(kt + 1) * ABKV * DHEAD,
                       Kl + (size_t)(kt + 1) * ABKV * DHEAD, DHEAD, t);
            CP_COMMIT();
        }

        // ---- online softmax (base-2); round P through fp16 ----
        float tm0 = s[0][0], tm1 = s[0][2];
#pragma unroll
        for (int nj = 0; nj < 16; ++nj) {
            tm0 = fmaxf(tm0, fmaxf(s[nj][0], s[nj][1]));
            tm1 = fmaxf(tm1, fmaxf(s[nj][2], s[nj][3]));
        }
        tm0 = fmaxf(tm0, __shfl_xor_sync(0xffffffffu, tm0, 1));
        tm0 = fmaxf(tm0, __shfl_xor_sync(0xffffffffu, tm0, 2));
        tm1 = fmaxf(tm1, __shfl_xor_sync(0xffffffffu, tm1, 1));
        tm1 = fmaxf(tm1, __shfl_xor_sync(0xffffffffu, tm1, 2));
        const float nm0 = fmaxf(m0, tm0), nm1 = fmaxf(m1, tm1);
        const float cr0 = ex2f(m0 - nm0), cr1 = ex2f(m1 - nm1);
        float sum0 = 0.f, sum1 = 0.f;
#pragma unroll
        for (int nj = 0; nj < 16; ++nj) {
            const uint32_t p01 = packh2(ex2f(s[nj][0] - nm0), ex2f(s[nj][1] - nm0));
            const uint32_t p23 = packh2(ex2f(s[nj][2] - nm1), ex2f(s[nj][3] - nm1));
            const float2 f01 = h2f2(p01), f23 = h2f2(p23);
            s[nj][0] = f01.x; s[nj][1] = f01.y;
            s[nj][2] = f23.x; s[nj][3] = f23.y;
            sum0 += f01.x + f01.y;
            sum1 += f23.x + f23.y;
        }
        sum0 += __shfl_xor_sync(0xffffffffu, sum0, 1);
        sum0 += __shfl_xor_sync(0xffffffffu, sum0, 2);
        sum1 += __shfl_xor_sync(0xffffffffu, sum1, 1);
        sum1 += __shfl_xor_sync(0xffffffffu, sum1, 2);
        l0 = l0 * cr0 + sum0;
        l1 = l1 * cr1 + sum1;
        m0 = nm0; m1 = nm1;
#pragma unroll
        for (int nj = 0; nj < 16; ++nj) {
            o[nj][0] *= cr0; o[nj][1] *= cr0;
            o[nj][2] *= cr1; o[nj][3] *= cr1;
        }

        // ---- O += P V ----
        CP_WAIT(1);
        __syncthreads();

#pragma unroll
        for (int j = 0; j < 8; ++j) {
            uint32_t ap[4];
            ap[0] = packh2(s[2 * j][0],     s[2 * j][1]);
            ap[1] = packh2(s[2 * j][2],     s[2 * j][3]);
            ap[2] = packh2(s[2 * j + 1][0], s[2 * j + 1][1]);
            ap[3] = packh2(s[2 * j + 1][2], s[2 * j + 1][3]);
#pragma unroll
            for (int bj = 0; bj < 8; ++bj) {
                uint32_t vh[4];
                ldmat4(vh, sb + AV + SWB(bj * 16 + rowB, 2 * j + chB));
                mma_f16(o[2 * bj],     ap, &vh[0]);
                mma_f16(o[2 * bj + 1], ap, &vh[2]);
            }
        }
        __syncthreads();
        if (kt + 1 < NKT_S) {
            issue_single(sb + AV, Vt + (size_t)(kt + 1) * ABKV, MCACHE, t);
            CP_COMMIT();
            CP_WAIT(1);
            __syncthreads();
        }
    }

    // ---- write unnormalized partial + (m, l) ----
    float* Op = g_Op[kvs];
    const int row0 = q0 + q0w + (lane >> 2);
    const int qc = (lane & 3) * 2;
    const size_t rbase = (size_t)h * SEQL;
#pragma unroll
    for (int nj = 0; nj < 16; ++nj) {
        const int d0 = nj * 8 + qc;
        float* p0 = Op + (rbase + row0) * DHEAD + d0;
        float* p1 = Op + (rbase + row0 + 8) * DHEAD + d0;
        *reinterpret_cast<float2*>(p0) = make_float2(o[nj][0], o[nj][1]);
        *reinterpret_cast<float2*>(p1) = make_float2(o[nj][2], o[nj][3]);
    }
    if ((lane & 3) == 0) {
        g_Pm[kvs][rbase + row0]     = m0;
        g_Pl[kvs][rbase + row0]     = l0;
        g_Pm[kvs][rbase + row0 + 8] = m1;
        g_Pl[kvs][rbase + row0 + 8] = l1;
    }
}

// ======================= 2b) combine: merge 2 splits via log-sum-exp =========
// One warp per row; lane covers 32 float4 = 128 d values.
__global__ void __launch_bounds__(256)
attn_combine(float* __restrict__ out) {
    const int lane = threadIdx.x & 31;
    const int wrow = threadIdx.x >> 5;
    const size_t row = (size_t)blockIdx.x * 8 + wrow;   // h*SEQL + q
    const float m0 = g_Pm[0][row], m1 = g_Pm[1][row];
    const float l0 = g_Pl[0][row], l1 = g_Pl[1][row];
    const float M  = fmaxf(m0, m1);
    const float w0 = ex2f(m0 - M), w1 = ex2f(m1 - M);
    const float inv = __fdividef(1.f, w0 * l0 + w1 * l1);
    const float c0 = w0 * inv, c1 = w1 * inv;
    const size_t base = row * DHEAD + lane * 4;
    const float4 a = *reinterpret_cast<const float4*>(&g_Op[0][base]);
    const float4 b = *reinterpret_cast<const float4*>(&g_Op[1][base]);
    *reinterpret_cast<float4*>(out + base) =
        make_float4(a.x * c0 + b.x * c1, a.y * c0 + b.y * c1,
                    a.z * c0 + b.z * c1, a.w * c0 + b.w * c1);
}

// ======================= launch =======================
extern "C" void kernel_launch(void* const* d_in, const int* in_sizes, int n_in,
                              void* d_out, int out_size) {
    const float* X  = (const float*)d_in[0];
    const float* Wq = (const float*)d_in[1];
    const float* Wk = (const float*)d_in[2];
    const float* Wv = (const float*)d_in[3];
    const float* cK = (const float*)d_in[4];
    const float* cV = (const float*)d_in[5];
    const int*   Pp = (const int*)d_in[6];

    convert_cacheK<<<1024, 256>>>((const float4*)cK);
    dim3 vgrid(MCACHE / 32, DHEAD / 32, HEADS);
    convert_cacheV<<<vgrid, 256>>>(cV);
    convert_X_kernel<<<2048, 256>>>((const float4*)X);
    dim3 wgrid(NMODEL / 32, NMODEL / 32, 3);
    convert_W_kernel<<<wgrid, 256>>>(Wq, Wk, Wv);

    cudaFuncSetAttribute(qkv_gemm_mma, cudaFuncAttributeMaxDynamicSharedMemorySize,
                         G_SMEM);
    dim3 ggrid(SEQL / GBM, NMODEL / GBN, 3);
    qkv_gemm_mma<<<ggrid, 256, G_SMEM>>>(Pp);

    cudaFuncSetAttribute(attn_tc, cudaFuncAttributeMaxDynamicSharedMemorySize,
                         A_SMEM);
    dim3 agrid(SEQL / ABQ, HEADS, KVSPLIT);
    attn_tc<<<agrid, 256, A_SMEM>>>();

    attn_combine<<<HEADS * SEQL / 8, 256>>>((float*)d_out);
}

// round 15
// speedup vs baseline: 1.0552x; 1.0058x over previous
#include <cuda_runtime.h>
#include <cuda_fp16.h>
#include <cstdint>

// Problem dims (fixed by the reference)
#define SEQL   2048
#define NMODEL 4096
#define HEADS  32
#define DHEAD  128
#define MCACHE 4096
#define LOG2E  1.4426950408889634f
#define KVSPLIT 2
#define MSPLIT (MCACHE / KVSPLIT)

// ======================= family-portable PTX helpers =======================
__device__ __forceinline__ uint32_t smem_to_u32(const void* p) {
    uint32_t a;
    asm("{ .reg .u64 t; cvta.to.shared.u64 t, %1; cvt.u32.u64 %0, t; }"
        : "=r"(a) : "l"(p));
    return a;
}
__device__ __forceinline__ void mma_f16(float* c, const uint32_t* a, const uint32_t* b) {
    asm volatile(
        "mma.sync.aligned.m16n8k16.row.col.f32.f16.f16.f32 "
        "{%0,%1,%2,%3}, {%4,%5,%6,%7}, {%8,%9}, {%0,%1,%2,%3};"
        : "+f"(c[0]), "+f"(c[1]), "+f"(c[2]), "+f"(c[3])
        : "r"(a[0]), "r"(a[1]), "r"(a[2]), "r"(a[3]), "r"(b[0]), "r"(b[1]));
}
__device__ __forceinline__ void ldmat4(uint32_t* r, uint32_t addr) {
    asm volatile("ldmatrix.sync.aligned.m8n8.x4.shared.b16 {%0,%1,%2,%3}, [%4];"
        : "=r"(r[0]), "=r"(r[1]), "=r"(r[2]), "=r"(r[3]) : "r"(addr));
}
__device__ __forceinline__ void cpasync16(uint32_t dst, const void* src) {
    asm volatile("cp.async.cg.shared.global [%0], [%1], 16;" :: "r"(dst), "l"(src));
}
#define CP_COMMIT() asm volatile("cp.async.commit_group;" ::: "memory")
#define CP_WAIT(n)  asm volatile("cp.async.wait_group %0;" :: "n"(n) : "memory")

// pack two f32 -> f16x2 register (low half = first arg)
__device__ __forceinline__ uint32_t packh2(float lo, float hi) {
    uint32_t r;
    asm("cvt.rn.f16x2.f32 %0, %1, %2;" : "=r"(r) : "f"(hi), "f"(lo));
    return r;
}
__device__ __forceinline__ float2 h2f2(uint32_t u) {
    __half2 h = *reinterpret_cast<__half2*>(&u);
    return __half22float2(h);
}
// MUFU.EX2 (base-2 exp, approx: 2^-22 rel err)
__device__ __forceinline__ float ex2f(float x) {
    float y;
    asm("ex2.approx.f32 %0, %1;" : "=f"(y) : "f"(x));
    return y;
}

// ======================= scratch (device globals) =======================
__device__ __half g_Qhi[(size_t)HEADS * SEQL * DHEAD];
__device__ __half g_Qlo[(size_t)HEADS * SEQL * DHEAD];
__device__ __half g_Khi[(size_t)HEADS * MCACHE * DHEAD];   // pre-scaled by LOG2E
__device__ __half g_Klo[(size_t)HEADS * MCACHE * DHEAD];
__device__ __half g_Vt[(size_t)HEADS * DHEAD * MCACHE];    // [h][d][m], single fp16
__device__ __half g_Xhi[(size_t)SEQL * NMODEL];
__device__ __half g_Xlo[(size_t)SEQL * NMODEL];
__device__ __half g_Whi[3][(size_t)NMODEL * NMODEL];       // transposed: [n][k]
__device__ __half g_Wlo[3][(size_t)NMODEL * NMODEL];
// split-KV partials
__device__ float g_Op[KVSPLIT][(size_t)HEADS * SEQL * DHEAD];
__device__ float g_Pm[KVSPLIT][(size_t)HEADS * SEQL];
__device__ float g_Pl[KVSPLIT][(size_t)HEADS * SEQL];

// ======================= 0) fused conversion kernel ==========================
// blockIdx ranges:  [0, 49152)         W transpose+split (longest first)
//                   [49152, 65536)     cacheV transpose
//                   [65536, 67584)     cacheK split (grid-stride, 2048 blocks)
//                   [67584, 69632)     X split (grid-stride, 2048 blocks)
#define CVT_W_BLKS  49152
#define CVT_V_BLKS  16384
#define CVT_K_BLKS  2048
#define CVT_X_BLKS  2048
#define CVT_TOTAL   (CVT_W_BLKS + CVT_V_BLKS + CVT_K_BLKS + CVT_X_BLKS)

__global__ void __launch_bounds__(256)
convert_all(const float* __restrict__ cK,
            const float* __restrict__ cV,
            const float* __restrict__ X,
            const float* __restrict__ Wq,
            const float* __restrict__ Wk,
            const float* __restrict__ Wv) {
    __shared__ float tile[32][33];
    const int b = blockIdx.x;
    const int t = threadIdx.x;

    if (b < CVT_W_BLKS) {
        // ---- W transpose + split (half2 stores along k) ----
        const int z   = b / 16384;
        const int rem = b % 16384;
        const int n0  = (rem & 127) * 32;
        const int k0  = (rem >> 7) * 32;
        const float* __restrict__ W = (z == 0) ? Wq : ((z == 1) ? Wk : Wv);
        const int tx = t & 31, ty = t >> 5;
#pragma unroll
        for (int i = 0; i < 4; i++)
            tile[ty + 8 * i][tx] = W[(size_t)(k0 + ty + 8 * i) * NMODEL + n0 + tx];
        __syncthreads();
        uint32_t* Hi2 = reinterpret_cast<uint32_t*>(g_Whi[z]);
        uint32_t* Lo2 = reinterpret_cast<uint32_t*>(g_Wlo[z]);
        const int kp  = t & 15;
        const int nl0 = t >> 4;
#pragma unroll
        for (int j = 0; j < 2; j++) {
            const int nl = nl0 + 16 * j;
            const float v0 = tile[2 * kp][nl];
            const float v1 = tile[2 * kp + 1][nl];
            const uint32_t hi = packh2(v0, v1);
            const float2 f = h2f2(hi);
            const uint32_t lo = packh2(v0 - f.x, v1 - f.y);
            const size_t o2 = ((size_t)(n0 + nl) * NMODEL + k0) / 2 + kp;
            Hi2[o2] = hi;
            Lo2[o2] = lo;
        }
    } else if (b < CVT_W_BLKS + CVT_V_BLKS) {
        // ---- cacheV transpose -> fp16 (half2 stores along m) ----
        const int rem = b - CVT_W_BLKS;
        const int m0 = (rem & 127) * 32;
        const int d0 = ((rem >> 7) & 3) * 32;
        const int h  = rem >> 9;
        const int tx = t & 31, ty = t >> 5;
#pragma unroll
        for (int i = 0; i < 4; i++)
            tile[ty + 8 * i][tx] =
                cV[((size_t)h * MCACHE + m0 + ty + 8 * i) * DHEAD + d0 + tx];
        __syncthreads();
        const int kp = t & 15;
        const int dl0 = t >> 4;
#pragma unroll
        for (int j = 0; j < 2; j++) {
            const int dl = dl0 + 16 * j;
            const float v0 = tile[2 * kp][dl];
            const float v1 = tile[2 * kp + 1][dl];
            const uint32_t hv = packh2(v0, v1);
            const size_t o2 = (((size_t)h * DHEAD + d0 + dl) * MCACHE + m0) / 2 + kp;
            reinterpret_cast<uint32_t*>(g_Vt)[o2] = hv;
        }
    } else if (b < CVT_W_BLKS + CVT_V_BLKS + CVT_K_BLKS) {
        // ---- cacheK split (scaled by LOG2E), grid-stride ----
        const int bb = b - (CVT_W_BLKS + CVT_V_BLKS);
        const int n = HEADS * MCACHE * DHEAD / 4;
        const float4* cK4 = reinterpret_cast<const float4*>(cK);
        __half2* Hi = reinterpret_cast<__half2*>(g_Khi);
        __half2* Lo = reinterpret_cast<__half2*>(g_Klo);
        for (int i = bb * 256 + t; i < n; i += CVT_K_BLKS * 256) {
            float4 v = cK4[i];
            v.x *= LOG2E; v.y *= LOG2E; v.z *= LOG2E; v.w *= LOG2E;
            const uint32_t h0 = packh2(v.x, v.y);
            const uint32_t h1 = packh2(v.z, v.w);
            const float2 f0 = h2f2(h0), f1 = h2f2(h1);
            Hi[2 * i]     = *reinterpret_cast<const __half2*>(&h0);
            Hi[2 * i + 1] = *reinterpret_cast<const __half2*>(&h1);
            const uint32_t l0 = packh2(v.x - f0.x, v.y - f0.y);
            const uint32_t l1 = packh2(v.z - f1.x, v.w - f1.y);
            Lo[2 * i]     = *reinterpret_cast<const __half2*>(&l0);
            Lo[2 * i + 1] = *reinterpret_cast<const __half2*>(&l1);
        }
    } else {
        // ---- X split, grid-stride ----
        const int bb = b - (CVT_W_BLKS + CVT_V_BLKS + CVT_K_BLKS);
        const int n = SEQL * NMODEL / 4;
        const float4* X4 = reinterpret_cast<const float4*>(X);
        __half2* Hi = reinterpret_cast<__half2*>(g_Xhi);
        __half2* Lo = reinterpret_cast<__half2*>(g_Xlo);
        for (int i = bb * 256 + t; i < n; i += CVT_X_BLKS * 256) {
            const float4 v = X4[i];
            const uint32_t h0 = packh2(v.x, v.y);
            const uint32_t h1 = packh2(v.z, v.w);
            const float2 f0 = h2f2(h0), f1 = h2f2(h1);
            Hi[2 * i]     = *reinterpret_cast<const __half2*>(&h0);
            Hi[2 * i + 1] = *reinterpret_cast<const __half2*>(&h1);
            const uint32_t l0 = packh2(v.x - f0.x, v.y - f0.y);
            const uint32_t l1 = packh2(v.z - f1.x, v.w - f1.y);
            Lo[2 * i]     = *reinterpret_cast<const __half2*>(&l0);
            Lo[2 * i + 1] = *reinterpret_cast<const __half2*>(&l1);
        }
    }
}

// ======================= 1) split-fp16 mma.sync QKV GEMM (R9/R11 winner) ============
#define GBM 128
#define GBN 128
#define GBK 32
#define G_ITERS (NMODEL / GBK)
#define G_STAGE 32768
#define G_SMEM  (3 * G_STAGE)

#define SWZ(row, ch) ((uint32_t)((row) * 64 + ((((ch) ^ (((row) >> 1) & 3))) << 4)))
#define SWZ4(m, d) ((uint32_t)((m) * 128 + ((d) ^ ((m) & 31))))

__global__ void __launch_bounds__(256, 2)
qkv_gemm_mma(const int* __restrict__ Pp) {
    extern __shared__ char smg[];
    const uint32_t sb = smem_to_u32(smg);
    const int t = threadIdx.x, lane = t & 31, wid = t >> 5;
    const int mt = blockIdx.x;
    const int nt = blockIdx.y;
    const int z  = blockIdx.z;
    const int wm = wid & 1;
    const int wn = wid >> 1;
    const bool full = (z != 2);

    const __half* __restrict__ Ah = g_Xhi + (size_t)(mt * GBM) * NMODEL;
    const __half* __restrict__ Al = g_Xlo + (size_t)(mt * GBM) * NMODEL;
    const __half* __restrict__ Bh = g_Whi[z] + (size_t)(nt * GBN) * NMODEL;
    const __half* __restrict__ Bl = g_Wlo[z] + (size_t)(nt * GBN) * NMODEL;

    float acc[4][4][4];
#pragma unroll
    for (int i = 0; i < 4; i++)
#pragma unroll
        for (int j = 0; j < 4; j++)
#pragma unroll
            for (int r = 0; r < 4; r++) acc[i][j][r] = 0.f;

    const int r0 = t >> 2, c0 = t & 3;
    const int r1 = (t + 256) >> 2, c1 = t & 3;

#define G_ISSUE(slot, k0)                                                      \
    do {                                                                       \
        const uint32_t stg = sb + (uint32_t)(slot) * G_STAGE;                  \
        const size_t ga0 = (size_t)r0 * NMODEL + (k0) + c0 * 8;                \
        const size_t ga1 = (size_t)r1 * NMODEL + (k0) + c1 * 8;                \
        cpasync16(stg + SWZ(r0, c0), Ah + ga0);                                \
        cpasync16(stg + SWZ(r1, c1), Ah + ga1);                                \
        if (full) {                                                            \
            cpasync16(stg + 8192 + SWZ(r0, c0), Al + ga0);                     \
            cpasync16(stg + 8192 + SWZ(r1, c1), Al + ga1);                     \
        }                                                                      \
        cpasync16(stg + 16384 + SWZ(r0, c0), Bh + ga0);                        \
        cpasync16(stg + 16384 + SWZ(r1, c1), Bh + ga1);                        \
        cpasync16(stg + 24576 + SWZ(r0, c0), Bl + ga0);                        \
        cpasync16(stg + 24576 + SWZ(r1, c1), Bl + ga1);                        \
        CP_COMMIT();                                                           \
    } while (0)

    G_ISSUE(0, 0);
    G_ISSUE(1, GBK);

    const int rowA = wm * 64 + (lane & 7) + ((lane >> 3) & 1) * 8;
    const int chA  = (lane >> 4);
    const int rowB = wn * 32 + (lane & 7) + ((lane & 16) ? 8 : 0);
    const int chB  = ((lane >> 3) & 1);

    int slot = 0, nslot = 2;
    for (int c = 0; c < G_ITERS; ++c) {
        if (c + 2 < G_ITERS) { CP_WAIT(1); } else { CP_WAIT(0); }
        __syncthreads();
        if (c + 2 < G_ITERS) {
            G_ISSUE(nslot, (c + 2) * GBK);
        }

        const uint32_t sA = sb + (uint32_t)slot * G_STAGE;
        const uint32_t sB = sA + 16384;
#pragma unroll
        for (int g = 0; g < 2; ++g) {
            uint32_t bh[2][4], bl[2][4];
#pragma unroll
            for (int bj = 0; bj < 2; ++bj) {
                const uint32_t ad = sB + SWZ(rowB + bj * 16, 2 * g + chB);
                ldmat4(bh[bj], ad);
                ldmat4(bl[bj], ad + 8192);
            }
#pragma unroll
            for (int mi = 0; mi < 4; ++mi) {
                uint32_t ah[4], al[4];
                const uint32_t ad = sA + SWZ(rowA + mi * 16, 2 * g + chA);
                ldmat4(ah, ad);
                if (full) ldmat4(al, ad + 8192);
#pragma unroll
                for (int nj = 0; nj < 4; ++nj) {
                    const uint32_t* bhp = &bh[nj >> 1][(nj & 1) * 2];
                    const uint32_t* blp = &bl[nj >> 1][(nj & 1) * 2];
                    mma_f16(acc[mi][nj], ah, bhp);
                    mma_f16(acc[mi][nj], ah, blp);
                    if (full) mma_f16(acc[mi][nj], al, bhp);
                }
            }
        }
        slot  = (slot == 2) ? 0 : slot + 1;
        nslot = (nslot == 2) ? 0 : nslot + 1;
    }
#undef G_ISSUE

    const int P = *Pp;
    const int qr = lane >> 2, qc = (lane & 3) * 2;

    if (z != 2) {
        const float scl = (z == 1) ? LOG2E : 1.f;
        __half* Dhi = (z == 0) ? g_Qhi : g_Khi;
        __half* Dlo = (z == 0) ? g_Qlo : g_Klo;
        const int rows  = (z == 0) ? SEQL : MCACHE;
        const int rbase = (z == 0) ? 0 : P;
#pragma unroll
        for (int mi = 0; mi < 4; ++mi)
#pragma unroll
            for (int nj = 0; nj < 4; ++nj) {
                const int m0 = mt * GBM + wm * 64 + mi * 16 + qr;
                const int n  = nt * GBN + wn * 32 + nj * 8 + qc;
                const int h = n >> 7, d0 = n & 127;
#pragma unroll
                for (int hv = 0; hv < 2; ++hv) {
                    const float v0 = acc[mi][nj][2 * hv] * scl;
                    const float v1 = acc[mi][nj][2 * hv + 1] * scl;
                    const uint32_t hi = packh2(v0, v1);
                    const float2 f = h2f2(hi);
                    const uint32_t lo = packh2(v0 - f.x, v1 - f.y);
                    const size_t o = ((size_t)h * rows + rbase + m0 + 8 * hv) * DHEAD + d0;
                    *reinterpret_cast<uint32_t*>(Dhi + o) = hi;
                    *reinterpret_cast<uint32_t*>(Dlo + o) = lo;
                }
            }
    } else {
        float* st = reinterpret_cast<float*>(smg);
        __syncthreads();
#pragma unroll
        for (int mi = 0; mi < 4; ++mi)
#pragma unroll
            for (int nj = 0; nj < 4; ++nj) {
                const int ml = wm * 64 + mi * 16 + qr;
                const int nl = wn * 32 + nj * 8 + qc;
                st[SWZ4(ml, nl)]         = acc[mi][nj][0];
                st[SWZ4(ml, nl + 1)]     = acc[mi][nj][1];
                st[SWZ4(ml + 8, nl)]     = acc[mi][nj][2];
                st[SWZ4(ml + 8, nl + 1)] = acc[mi][nj][3];
            }
        __syncthreads();
        const int d  = t >> 1;
        const int ms = (t & 1) * 64;
        const size_t ob = ((size_t)nt * DHEAD + d) * MCACHE + P + mt * GBM + ms;
#pragma unroll
        for (int mm = 0; mm < 64; mm += 2) {
            const uint32_t hv = packh2(st[SWZ4(ms + mm, d)], st[SWZ4(ms + mm + 1, d)]);
            *reinterpret_cast<uint32_t*>(g_Vt + ob + mm) = hv;
        }
    }
}

// ======================= 2) flash attention, split-KV (R14 winner) ==========
#define ABQ   128
#define ABKV  128
#define NKT_S (MSPLIT / ABKV)   // 16
#define SWB(row, ch) ((uint32_t)((row) * 256 + ((((ch) ^ ((row) & 7))) << 4)))
#define AQ_HI 0
#define AQ_LO 32768
#define AK_HI 65536
#define AK_LO 98304
#define AV    131072
#define A_SMEM 163840

__device__ __forceinline__ void issue_pair(uint32_t smhi, uint32_t smlo,
                                           const __half* ghi, const __half* glo,
                                           size_t rowstride, int t) {
#pragma unroll
    for (int i = 0; i < 8; ++i) {
        const int idx = t + i * 256;
        const int row = idx >> 4, ch = idx & 15;
        const size_t go = (size_t)row * rowstride + ch * 8;
        const uint32_t so = SWB(row, ch);
        cpasync16(smhi + so, ghi + go);
        cpasync16(smlo + so, glo + go);
    }
}
__device__ __forceinline__ void issue_single(uint32_t sm, const __half* g,
                                             size_t rowstride, int t) {
#pragma unroll
    for (int i = 0; i < 8; ++i) {
        const int idx = t + i * 256;
        const int row = idx >> 4, ch = idx & 15;
        cpasync16(sm + SWB(row, ch), g + (size_t)row * rowstride + ch * 8);
    }
}

__global__ void __launch_bounds__(256, 1)
attn_tc() {
    extern __shared__ char sma[];
    const uint32_t sb = smem_to_u32(sma);
    const int t = threadIdx.x, lane = t & 31, wid = t >> 5;
    const int h   = blockIdx.y;
    const int q0  = blockIdx.x * ABQ;
    const int kvs = blockIdx.z;
    const int q0w = wid * 16;

    const __half* __restrict__ Qh = g_Qhi + ((size_t)h * SEQL + q0) * DHEAD;
    const __half* __restrict__ Ql = g_Qlo + ((size_t)h * SEQL + q0) * DHEAD;
    const __half* __restrict__ Kh = g_Khi + ((size_t)h * MCACHE + kvs * MSPLIT) * DHEAD;
    const __half* __restrict__ Kl = g_Klo + ((size_t)h * MCACHE + kvs * MSPLIT) * DHEAD;
    const __half* __restrict__ Vt = g_Vt + (size_t)h * DHEAD * MCACHE + kvs * MSPLIT;

    issue_pair(sb + AQ_HI, sb + AQ_LO, Qh, Ql, DHEAD, t);
    issue_pair(sb + AK_HI, sb + AK_LO, Kh, Kl, DHEAD, t);
    CP_COMMIT();
    issue_single(sb + AV, Vt, MCACHE, t);
    CP_COMMIT();
    CP_WAIT(1);
    __syncthreads();

    const int rowA = (lane & 7) + ((lane >> 3) & 1) * 8;
    const int chA  = (lane >> 4);
    const int rowB = (lane & 7) + ((lane & 16) ? 8 : 0);
    const int chB  = ((lane >> 3) & 1);

    float m0 = -1e30f, m1 = -1e30f, l0 = 0.f, l1 = 0.f;
    float o[16][4];
#pragma unroll
    for (int i = 0; i < 16; i++)
#pragma unroll
        for (int r = 0; r < 4; r++) o[i][r] = 0.f;

    for (int kt = 0; kt < NKT_S; ++kt) {
        float s[16][4];
#pragma unroll
        for (int i = 0; i < 16; i++)
#pragma unroll
            for (int r = 0; r < 4; r++) s[i][r] = 0.f;

#pragma unroll
        for (int ks = 0; ks < 8; ++ks) {
            uint32_t ah[4], al[4];
            const uint32_t qa = sb + SWB(q0w + rowA, 2 * ks + chA);
            ldmat4(ah, qa + AQ_HI);
            ldmat4(al, qa + AQ_LO);
#pragma unroll
            for (int bj = 0; bj < 8; ++bj) {
                uint32_t bh[4], bl[4];
                const uint32_t ka = sb + SWB(bj * 16 + rowB, 2 * ks + chB);
                ldmat4(bh, ka + AK_HI);
                ldmat4(bl, ka + AK_LO);
                mma_f16(s[2 * bj],     ah, &bh[0]);
                mma_f16(s[2 * bj + 1], ah, &bh[2]);
                mma_f16(s[2 * bj],     ah, &bl[0]);
                mma_f16(s[2 * bj + 1], ah, &bl[2]);
                mma_f16(s[2 * bj],     al, &bh[0]);
                mma_f16(s[2 * bj + 1], al, &bh[2]);
            }
        }
        __syncthreads();
        if (kt + 1 < NKT_S) {
            issue_pair(sb + AK_HI, sb + AK_LO,
                       Kh + (size_t)(kt + 1) * ABKV * DHEAD,
                       Kl + (size_t)(kt + 1) * ABKV * DHEAD, DHEAD, t);
            CP_COMMIT();
        }

        float tm0 = s[0][0], tm1 = s[0][2];
#pragma unroll
        for (int nj = 0; nj < 16; ++nj) {
            tm0 = fmaxf(tm0, fmaxf(s[nj][0], s[nj][1]));
            tm1 = fmaxf(tm1, fmaxf(s[nj][2], s[nj][3]));
        }
        tm0 = fmaxf(tm0, __shfl_xor_sync(0xffffffffu, tm0, 1));
        tm0 = fmaxf(tm0, __shfl_xor_sync(0xffffffffu, tm0, 2));
        tm1 = fmaxf(tm1, __shfl_xor_sync(0xffffffffu, tm1, 1));
        tm1 = fmaxf(tm1, __shfl_xor_sync(0xffffffffu, tm1, 2));
        const float nm0 = fmaxf(m0, tm0), nm1 = fmaxf(m1, tm1);
        const float cr0 = ex2f(m0 - nm0), cr1 = ex2f(m1 - nm1);
        float sum0 = 0.f, sum1 = 0.f;
#pragma unroll
        for (int nj = 0; nj < 16; ++nj) {
            const uint32_t p01 = packh2(ex2f(s[nj][0] - nm0), ex2f(s[nj][1] - nm0));
            const uint32_t p23 = packh2(ex2f(s[nj][2] - nm1), ex2f(s[nj][3] - nm1));
            const float2 f01 = h2f2(p01), f23 = h2f2(p23);
            s[nj][0] = f01.x; s[nj][1] = f01.y;
            s[nj][2] = f23.x; s[nj][3] = f23.y;
            sum0 += f01.x + f01.y;
            sum1 += f23.x + f23.y;
        }
        sum0 += __shfl_xor_sync(0xffffffffu, sum0, 1);
        sum0 += __shfl_xor_sync(0xffffffffu, sum0, 2);
        sum1 += __shfl_xor_sync(0xffffffffu, sum1, 1);
        sum1 += __shfl_xor_sync(0xffffffffu, sum1, 2);
        l0 = l0 * cr0 + sum0;
        l1 = l1 * cr1 + sum1;
        m0 = nm0; m1 = nm1;
#pragma unroll
        for (int nj = 0; nj < 16; ++nj) {
            o[nj][0] *= cr0; o[nj][1] *= cr0;
            o[nj][2] *= cr1; o[nj][3] *= cr1;
        }

        CP_WAIT(1);
        __syncthreads();

#pragma unroll
        for (int j = 0; j < 8; ++j) {
            uint32_t ap[4];
            ap[0] = packh2(s[2 * j][0],     s[2 * j][1]);
            ap[1] = packh2(s[2 * j][2],     s[2 * j][3]);
            ap[2] = packh2(s[2 * j + 1][0], s[2 * j + 1][1]);
            ap[3] = packh2(s[2 * j + 1][2], s[2 * j + 1][3]);
#pragma unroll
            for (int bj = 0; bj < 8; ++bj) {
                uint32_t vh[4];
                ldmat4(vh, sb + AV + SWB(bj * 16 + rowB, 2 * j + chB));
                mma_f16(o[2 * bj],     ap, &vh[0]);
                mma_f16(o[2 * bj + 1], ap, &vh[2]);
            }
        }
        __syncthreads();
        if (kt + 1 < NKT_S) {
            issue_single(sb + AV, Vt + (size_t)(kt + 1) * ABKV, MCACHE, t);
            CP_COMMIT();
            CP_WAIT(1);
            __syncthreads();
        }
    }

    float* Op = g_Op[kvs];
    const int row0 = q0 + q0w + (lane >> 2);
    const int qc = (lane & 3) * 2;
    const size_t rbase = (size_t)h * SEQL;
#pragma unroll
    for (int nj = 0; nj < 16; ++nj) {
        const int d0 = nj * 8 + qc;
        float* p0 = Op + (rbase + row0) * DHEAD + d0;
        float* p1 = Op + (rbase + row0 + 8) * DHEAD + d0;
        *reinterpret_cast<float2*>(p0) = make_float2(o[nj][0], o[nj][1]);
        *reinterpret_cast<float2*>(p1) = make_float2(o[nj][2], o[nj][3]);
    }
    if ((lane & 3) == 0) {
        g_Pm[kvs][rbase + row0]     = m0;
        g_Pl[kvs][rbase + row0]     = l0;
        g_Pm[kvs][rbase + row0 + 8] = m1;
        g_Pl[kvs][rbase + row0 + 8] = l1;
    }
}

// ======================= 2b) combine: merge 2 splits via log-sum-exp =========
__global__ void __launch_bounds__(256)
attn_combine(float* __restrict__ out) {
    const int lane = threadIdx.x & 31;
    const int wrow = threadIdx.x >> 5;
    const size_t row = (size_t)blockIdx.x * 8 + wrow;
    const float m0 = g_Pm[0][row], m1 = g_Pm[1][row];
    const float l0 = g_Pl[0][row], l1 = g_Pl[1][row];
    const float M  = fmaxf(m0, m1);
    const float w0 = ex2f(m0 - M), w1 = ex2f(m1 - M);
    const float inv = __fdividef(1.f, w0 * l0 + w1 * l1);
    const float c0 = w0 * inv, c1 = w1 * inv;
    const size_t base = row * DHEAD + lane * 4;
    const float4 a = *reinterpret_cast<const float4*>(&g_Op[0][base]);
    const float4 b = *reinterpret_cast<const float4*>(&g_Op[1][base]);
    *reinterpret_cast<float4*>(out + base) =
        make_float4(a.x * c0 + b.x * c1, a.y * c0 + b.y * c1,
                    a.z * c0 + b.z * c1, a.w * c0 + b.w * c1);
}

// ======================= launch =======================
extern "C" void kernel_launch(void* const* d_in, const int* in_sizes, int n_in,
                              void* d_out, int out_size) {
    const float* X  = (const float*)d_in[0];
    const float* Wq = (const float*)d_in[1];
    const float* Wk = (const float*)d_in[2];
    const float* Wv = (const float*)d_in[3];
    const float* cK = (const float*)d_in[4];
    const float* cV = (const float*)d_in[5];
    const int*   Pp = (const int*)d_in[6];

    // 0) fused conversions (one launch, all four workloads co-resident)
    convert_all<<<CVT_TOTAL, 256>>>(cK, cV, X, Wq, Wk, Wv);

    // 1) QKV projections
    cudaFuncSetAttribute(qkv_gemm_mma, cudaFuncAttributeMaxDynamicSharedMemorySize,
                         G_SMEM);
    dim3 ggrid(SEQL / GBM, NMODEL / GBN, 3);
    qkv_gemm_mma<<<ggrid, 256, G_SMEM>>>(Pp);

    // 2) split-KV attention + combine
    cudaFuncSetAttribute(attn_tc, cudaFuncAttributeMaxDynamicSharedMemorySize,
                         A_SMEM);
    dim3 agrid(SEQL / ABQ, HEADS, KVSPLIT);
    attn_tc<<<agrid, 256, A_SMEM>>>();

    attn_combine<<<HEADS * SEQL / 8, 256>>>((float*)d_out);
}